// round 15
// baseline (speedup 1.0000x reference)
#include <cuda_runtime.h>
#include <cstdint>

#define T_STEPS 256
#define B_SZ    16
#define IN_DIM  1024
#define N_NEUR  2048

#define ALPHA_C 0.9f
#define BETA_C  0.9f
#define TH_C    20.0f

#define NCAND 7
#define PLANE (T_STEPS * B_SZ * N_NEUR)

#define SCAN_BLOCKS  128
#define SCAN_THREADS 256

// ---------------- scratch (device globals: allocation-free) ----------------
__device__ float          g_curr[NCAND][PLANE];      // 7 x 33.5 MB candidate input currents
__device__ float          g_wrecT[N_NEUR * N_NEUR];  // 16.7 MB Wrec transposed
__device__ unsigned short g_masks16[2][N_NEUR];      // ping-pong majority spike masks
__device__ unsigned       g_S[N_NEUR][8];            // batch-0 spike bits over time
__device__ unsigned       g_bar_cnt;
__device__ volatile unsigned g_bar_gen;

// ---------------- init ----------------
__global__ void init_kernel() {
    int tid = threadIdx.x;
    for (int i = tid; i < N_NEUR; i += blockDim.x) {
        g_masks16[0][i] = 0;
        g_masks16[1][i] = 0;
    }
    if (tid == 0) { g_bar_cnt = 0u; g_bar_gen = 0u; }
}

// ============ scalar-chain GEMM candidate: kc-panel fold, single acc chain ============
// out[m,n] = fold_panels( asc-k FMA chain ) + bias[n]
#define GM 128
#define GN 128
#define GK 8
template <int KC>
__global__ __launch_bounds__(256) void input_gemm(
    const float* __restrict__ A, const float* __restrict__ Bm,
    const float* __restrict__ bias, float* __restrict__ out)
{
    __shared__ float As[GK][GM];
    __shared__ float Bs[GK][GN];
    const int bm = blockIdx.y * GM;
    const int bn = blockIdx.x * GN;
    const int tid = threadIdx.x;
    const int tx = tid & 15, ty = tid >> 4;
    const int lr = tid >> 1;
    const int lk = (tid & 1) * 4;

    float bias_r[8];
#pragma unroll
    for (int j = 0; j < 8; j++) bias_r[j] = bias[bn + tx * 8 + j];

    int chunk_idx = 0;
    for (int p0 = 0; p0 < IN_DIM; p0 += KC, ++chunk_idx) {
        const int p_end = (p0 + KC < IN_DIM) ? (p0 + KC) : IN_DIM;

        float acc[8][8];
#pragma unroll
        for (int i = 0; i < 8; i++)
#pragma unroll
            for (int j = 0; j < 8; j++) acc[i][j] = 0.0f;

        for (int k0 = p0; k0 < p_end; k0 += GK) {
            float4 a4 = *(const float4*)&A [(size_t)(bm + lr) * IN_DIM + k0 + lk];
            float4 b4 = *(const float4*)&Bm[(size_t)(bn + lr) * IN_DIM + k0 + lk];
            As[lk + 0][lr] = a4.x; As[lk + 1][lr] = a4.y; As[lk + 2][lr] = a4.z; As[lk + 3][lr] = a4.w;
            Bs[lk + 0][lr] = b4.x; Bs[lk + 1][lr] = b4.y; Bs[lk + 2][lr] = b4.z; Bs[lk + 3][lr] = b4.w;
            __syncthreads();
#pragma unroll
            for (int k = 0; k < GK; k++) {
                float ar[8], br[8];
#pragma unroll
                for (int i = 0; i < 8; i++) ar[i] = As[k][ty * 8 + i];
#pragma unroll
                for (int j = 0; j < 8; j++) br[j] = Bs[k][tx * 8 + j];
#pragma unroll
                for (int i = 0; i < 8; i++)
#pragma unroll
                    for (int j = 0; j < 8; j++) acc[i][j] = fmaf(ar[i], br[j], acc[i][j]);
            }
            __syncthreads();
        }

        const bool first = (chunk_idx == 0);
        const bool last  = (p_end == IN_DIM);
#pragma unroll
        for (int i = 0; i < 8; i++) {
            int row = bm + ty * 8 + i;
            float* cptr = &out[(size_t)row * N_NEUR + bn + tx * 8];
#pragma unroll
            for (int j = 0; j < 8; j++) {
                float v = first ? acc[i][j] : __fadd_rn(cptr[j], acc[i][j]);
                if (last) v = __fadd_rn(v, bias_r[j]);
                cptr[j] = v;
            }
        }
    }
}

// ============ 4-lane GEMM candidate: NEON-style vectorized reduction ============
// Per element: 4 lane accumulators over k mod 4 within each kc panel, combined
// pairwise ((l0+l1)+(l2+l3)) at panel end, panels folded left-associated.
template <int KC>
__global__ __launch_bounds__(256) void input_gemm_l4(
    const float* __restrict__ A, const float* __restrict__ Bm,
    const float* __restrict__ bias, float* __restrict__ out)
{
    __shared__ float As[8][64];
    __shared__ float Bs[8][64];
    const int bm = blockIdx.y * 64;
    const int bn = blockIdx.x * 64;
    const int tid = threadIdx.x;
    const int tx = tid & 15, ty = tid >> 4;

    float tot[4][4];
    float lac[4][4][4];
#pragma unroll
    for (int i = 0; i < 4; i++)
#pragma unroll
        for (int j = 0; j < 4; j++) {
            tot[i][j] = 0.0f;
#pragma unroll
            for (int l = 0; l < 4; l++) lac[i][j][l] = 0.0f;
        }

    bool first = true;
    for (int p0 = 0; p0 < IN_DIM; p0 += KC) {
        const int p_end = (p0 + KC < IN_DIM) ? (p0 + KC) : IN_DIM;
        for (int k0 = p0; k0 < p_end; k0 += 8) {
            for (int i2 = tid; i2 < 512; i2 += 256) {
                int r = i2 >> 3, kk = i2 & 7;
                As[kk][r] = A [(size_t)(bm + r) * IN_DIM + k0 + kk];
                Bs[kk][r] = Bm[(size_t)(bn + r) * IN_DIM + k0 + kk];
            }
            __syncthreads();
#pragma unroll
            for (int kk = 0; kk < 8; kk++) {
                const int ln = kk & 3;
                float ar[4], br[4];
#pragma unroll
                for (int i = 0; i < 4; i++) ar[i] = As[kk][ty * 4 + i];
#pragma unroll
                for (int j = 0; j < 4; j++) br[j] = Bs[kk][tx * 4 + j];
#pragma unroll
                for (int i = 0; i < 4; i++)
#pragma unroll
                    for (int j = 0; j < 4; j++)
                        lac[i][j][ln] = fmaf(ar[i], br[j], lac[i][j][ln]);
            }
            __syncthreads();
        }
        // panel end: pairwise combine lanes, fold
#pragma unroll
        for (int i = 0; i < 4; i++)
#pragma unroll
            for (int j = 0; j < 4; j++) {
                float h = __fadd_rn(__fadd_rn(lac[i][j][0], lac[i][j][1]),
                                    __fadd_rn(lac[i][j][2], lac[i][j][3]));
                tot[i][j] = first ? h : __fadd_rn(tot[i][j], h);
#pragma unroll
                for (int l = 0; l < 4; l++) lac[i][j][l] = 0.0f;
            }
        first = false;
    }

#pragma unroll
    for (int i = 0; i < 4; i++) {
        int row = bm + ty * 4 + i;
#pragma unroll
        for (int j = 0; j < 4; j++) {
            int col = bn + tx * 4 + j;
            out[(size_t)row * N_NEUR + col] = __fadd_rn(tot[i][j], bias[col]);
        }
    }
}

// ---------------- Wrec transpose: g_wrecT[j, n] = Wrec[n, j] ----------------
__global__ void transpose_wrec(const float* __restrict__ in) {
    __shared__ float tile[32][33];
    int x = blockIdx.x * 32 + threadIdx.x;
    int y0 = blockIdx.y * 32;
    for (int r = threadIdx.y; r < 32; r += 8)
        tile[r][threadIdx.x] = in[(size_t)(y0 + r) * N_NEUR + x];
    __syncthreads();
    int x2 = blockIdx.y * 32 + threadIdx.x;
    int y2 = blockIdx.x * 32;
    for (int r = threadIdx.y; r < 32; r += 8)
        g_wrecT[(size_t)(y2 + r) * N_NEUR + x2] = tile[threadIdx.x][r];
}

// ---------------- grid barrier (all SCAN_BLOCKS co-resident) ----------------
__device__ __forceinline__ void grid_barrier(unsigned target) {
    __syncthreads();
    if (threadIdx.x == 0) {
        __threadfence();
        unsigned v = atomicAdd(&g_bar_cnt, 1u);
        if (v == (unsigned)(SCAN_BLOCKS - 1)) {
            g_bar_cnt = 0u;
            __threadfence();
            g_bar_gen = target;
        } else {
            while (g_bar_gen < target) { }
            __threadfence();
        }
    }
    __syncthreads();
}

// ---------------- persistent ensemble scan kernel ----------------
// 7 candidate orderings per cell, all driven by the SHARED majority spike stream:
//   c0..c4: scalar asc chains with kc in {inf,512,320,248,200} (skip-zero exact)
//   c5:     4-lane pairwise, single panel;  c6: 4-lane pairwise, kc=248 fold
// Reset uses the cell's PREVIOUS MAJORITY SPIKE (algebraically == (mem>TH) at t-1),
// so candidate states stay ulp-close to the reference trajectory.
__global__ __launch_bounds__(SCAN_THREADS, 1) void scan_kernel(
    const float* __restrict__ b_rec, float* __restrict__ out_spk)
{
    __shared__ unsigned short s_mask[N_NEUR];
    __shared__ unsigned short s_list[8][N_NEUR];
    __shared__ unsigned       s_ball[8];

    const int tid    = threadIdx.x;
    const int w      = tid >> 5;
    const int lane   = tid & 31;
    const int ng     = blockIdx.x >> 1;
    const int bg     = blockIdx.x & 1;
    const int n_base = ng * 32;
    const int n      = n_base + lane;
    const int b      = bg * 8 + w;

    float syn[NCAND], mem[NCAND];
#pragma unroll
    for (int c = 0; c < NCAND; c++) { syn[c] = 0.0f; mem[c] = 0.0f; }
    float prev_spk = 0.0f;

    const float brec_v = b_rec[n];
    const float* __restrict__ colW = g_wrecT + n;
    const size_t cell = (size_t)b * N_NEUR + n;

    for (int t = 0; t < T_STEPS; ++t) {
        const int par = t & 1;

        ((uint4*)s_mask)[tid] = ((const uint4*)g_masks16[par])[tid];
        __syncthreads();

        // ascending active list for batch b (ballot compaction)
        int cnt = 0;
#pragma unroll 4
        for (int r = 0; r < 64; ++r) {
            const int j = r * 32 + lane;
            const unsigned bit = (s_mask[j] >> b) & 1u;
            const unsigned bal = __ballot_sync(0xffffffffu, bit);
            if (bit)
                s_list[w][cnt + __popc(bal & ((1u << lane) - 1u))] = (unsigned short)j;
            cnt += __popc(bal);
        }
        __syncwarp();

        // ---- 7 candidate rec-sums in one list walk ----
        const int kcv[5] = {1000000, 512, 320, 248, 200};
        float acc[5], tot[5];
        int   nb[5];
#pragma unroll
        for (int c = 0; c < 5; c++) { acc[c] = 0.0f; tot[c] = 0.0f; nb[c] = kcv[c]; }
        float p4[4] = {0.0f, 0.0f, 0.0f, 0.0f};
        float q4[4] = {0.0f, 0.0f, 0.0f, 0.0f};
        float tot6 = 0.0f;
        int   nb6  = 248;

        const unsigned short* __restrict__ lst = s_list[w];
#pragma unroll 2
        for (int i = 0; i < cnt; ++i) {
            const int j = lst[i];                         // warp-uniform
            const float wv = colW[(size_t)j * N_NEUR];
#pragma unroll
            for (int c = 0; c < 5; ++c) {
                while (j >= nb[c]) {                      // warp-uniform
                    tot[c] = __fadd_rn(tot[c], acc[c]);
                    acc[c] = 0.0f;
                    nb[c] += kcv[c];
                }
                acc[c] = __fadd_rn(acc[c], wv);
            }
            while (j >= nb6) {
                tot6 = __fadd_rn(tot6, __fadd_rn(__fadd_rn(q4[0], q4[1]),
                                                 __fadd_rn(q4[2], q4[3])));
                q4[0] = q4[1] = q4[2] = q4[3] = 0.0f;
                nb6 += 248;
            }
            const int ln = j & 3;                         // warp-uniform
            if      (ln == 0) { p4[0] = __fadd_rn(p4[0], wv); q4[0] = __fadd_rn(q4[0], wv); }
            else if (ln == 1) { p4[1] = __fadd_rn(p4[1], wv); q4[1] = __fadd_rn(q4[1], wv); }
            else if (ln == 2) { p4[2] = __fadd_rn(p4[2], wv); q4[2] = __fadd_rn(q4[2], wv); }
            else              { p4[3] = __fadd_rn(p4[3], wv); q4[3] = __fadd_rn(q4[3], wv); }
        }

        float T[NCAND];
#pragma unroll
        for (int c = 0; c < 5; c++) T[c] = __fadd_rn(tot[c], acc[c]);
        T[5] = __fadd_rn(__fadd_rn(p4[0], p4[1]), __fadd_rn(p4[2], p4[3]));
        T[6] = __fadd_rn(tot6, __fadd_rn(__fadd_rn(q4[0], q4[1]),
                                         __fadd_rn(q4[2], q4[3])));

        // ---- state updates + majority vote ----
        const float reset = prev_spk * TH_C;              // exact: 0 or 20
        const size_t toff = (size_t)t * B_SZ * N_NEUR + cell;
        int v = 0;
#pragma unroll
        for (int c = 0; c < NCAND; c++) {
            const float cu = g_curr[c][toff];
            syn[c] = __fadd_rn(__fadd_rn(fmaf(ALPHA_C, syn[c], cu), T[c]), brec_v);
            mem[c] = __fsub_rn(fmaf(BETA_C, mem[c], syn[c]), reset);
            v += (mem[c] > TH_C) ? 1 : 0;
        }
        const float spike = (v >= 4) ? 1.0f : 0.0f;
        prev_spk = spike;

        out_spk[toff] = spike;

        const unsigned bal = __ballot_sync(0xffffffffu, spike != 0.0f);
        if (lane == 0) s_ball[w] = bal;
        __syncthreads();
        if (tid < 32) {
            unsigned m = 0u;
#pragma unroll
            for (int ww = 0; ww < 8; ++ww)
                m |= ((s_ball[ww] >> lane) & 1u) << ww;
            ((unsigned char*)&g_masks16[par ^ 1][n_base + lane])[bg] = (unsigned char)m;
            __threadfence();
        }

        grid_barrier((unsigned)(t + 1));
    }
}

// ---------------- batch-0 spike bit-vectors over time ----------------
__global__ void build_S(const float* __restrict__ spk) {
    int idx = blockIdx.x * blockDim.x + threadIdx.x;
    if (idx >= N_NEUR * 8) return;
    int n = idx >> 3, w0 = idx & 7;
    unsigned m = 0u;
#pragma unroll
    for (int k = 0; k < 32; k++) {
        int t = w0 * 32 + k;
        if (spk[(size_t)t * B_SZ * N_NEUR + n] != 0.0f) m |= (1u << k);
    }
    g_S[n][w0] = m;
}

// ---------------- STDP closed form: W = clip(W0 + delta*cnt, -1, 1) ----------------
__global__ __launch_bounds__(256) void stdp_kernel(
    const float* __restrict__ W0, float* __restrict__ Wout, float delta)
{
    const int n = blockIdx.y;
    const int j = blockIdx.x * 256 + threadIdx.x;
    __shared__ unsigned Sn[8];
    if (threadIdx.x < 8) Sn[threadIdx.x] = g_S[n][threadIdx.x];
    __syncthreads();

    unsigned Sj[8];
#pragma unroll
    for (int w = 0; w < 8; w++) Sj[w] = g_S[j][w];

    int cnt = 0;
    unsigned carry = 0u;
#pragma unroll
    for (int w = 0; w < 8; w++) {
        unsigned sh = (Sj[w] << 1) | carry;
        carry = Sj[w] >> 31;
        cnt += __popc(Sn[w] & sh);
    }

    float wv = W0[(size_t)n * N_NEUR + j];
    float r = wv + delta * (float)cnt;
    r = fmaxf(r, -1.0f);
    r = fminf(r, 1.0f);
    Wout[(size_t)n * N_NEUR + j] = r;
}

// ---------------- launch ----------------
extern "C" void kernel_launch(void* const* d_in, const int* in_sizes, int n_in,
                              void* d_out, int out_size)
{
    const float* x     = (const float*)d_in[0];
    const float* Win   = (const float*)d_in[1];
    const float* b_in  = (const float*)d_in[2];
    const float* Wrec  = (const float*)d_in[3];
    const float* b_rec = (const float*)d_in[4];
    const float* Wlsm  = (const float*)d_in[5];

    float* out_spk = (float*)d_out;
    float* out_W   = (float*)d_out + (size_t)PLANE;

    float* curr_base;
    cudaGetSymbolAddress((void**)&curr_base, g_curr);

    init_kernel<<<1, 256>>>();

    dim3 ggrid(N_NEUR / GN, (T_STEPS * B_SZ) / GM);      // (16, 32)
    input_gemm<1024><<<ggrid, 256>>>(x, Win, b_in, curr_base + 0 * (size_t)PLANE);
    input_gemm< 512><<<ggrid, 256>>>(x, Win, b_in, curr_base + 1 * (size_t)PLANE);
    input_gemm< 320><<<ggrid, 256>>>(x, Win, b_in, curr_base + 2 * (size_t)PLANE);
    input_gemm< 248><<<ggrid, 256>>>(x, Win, b_in, curr_base + 3 * (size_t)PLANE);
    input_gemm< 200><<<ggrid, 256>>>(x, Win, b_in, curr_base + 4 * (size_t)PLANE);

    dim3 lgrid(N_NEUR / 64, (T_STEPS * B_SZ) / 64);      // (32, 64)
    input_gemm_l4<1024><<<lgrid, 256>>>(x, Win, b_in, curr_base + 5 * (size_t)PLANE);
    input_gemm_l4< 248><<<lgrid, 256>>>(x, Win, b_in, curr_base + 6 * (size_t)PLANE);

    dim3 tgrid(N_NEUR / 32, N_NEUR / 32);
    transpose_wrec<<<tgrid, dim3(32, 8)>>>(Wrec);

    scan_kernel<<<SCAN_BLOCKS, SCAN_THREADS>>>(b_rec, out_spk);

    build_S<<<(N_NEUR * 8) / 256, 256>>>(out_spk);

    const float stdp_delta = (expf(-1.0f / 20.0f) - expf(1.0f / 20.0f)) * 0.001f;
    stdp_kernel<<<dim3(N_NEUR / 256, N_NEUR), 256>>>(Wlsm, out_W, stdp_delta);
}

// round 16
// speedup vs baseline: 1.5572x; 1.5572x over previous
#include <cuda_runtime.h>
#include <cstdint>

#define T_STEPS 256
#define B_SZ    16
#define IN_DIM  1024
#define N_NEUR  2048

#define ALPHA_C 0.9f
#define BETA_C  0.9f
#define TH_C    20.0f

#define NCAND 7
#define PLANE (T_STEPS * B_SZ * N_NEUR)

#define SCAN_BLOCKS  128
#define SCAN_THREADS 256

// ---------------- scratch (device globals: allocation-free) ----------------
__device__ float          g_curr[NCAND][PLANE];      // 7 x 33.5 MB candidate input currents
__device__ float          g_wrecT[N_NEUR * N_NEUR];  // 16.7 MB Wrec transposed
__device__ unsigned       g_bitmaps[2][B_SZ][64];    // ping-pong per-batch spike bitmaps
__device__ unsigned short g_lists[B_SZ][N_NEUR];     // per-batch ascending active lists
__device__ int            g_cnt[B_SZ];
__device__ unsigned       g_S[N_NEUR][8];            // batch-0 spike bits over time
__device__ unsigned       g_bar_cnt;
__device__ volatile unsigned g_bar_gen;

// ---------------- init ----------------
__global__ void init_kernel() {
    int tid = threadIdx.x;
    for (int i = tid; i < 2 * B_SZ * 64; i += blockDim.x)
        ((unsigned*)g_bitmaps)[i] = 0u;
    if (tid < B_SZ) g_cnt[tid] = 0;
    if (tid == 0) { g_bar_cnt = 0u; g_bar_gen = 0u; }
}

// ============ scalar-chain GEMM candidate: kc-panel fold, single acc chain ============
// out[m,n] = fold_panels( ascending-k FMA chain ) + bias[n]; panels folded in regs
// (same value sequence as gmem staging). Register double-buffered global loads.
#define GM 128
#define GN 128
template <int KC>
__global__ __launch_bounds__(256) void input_gemm(
    const float* __restrict__ A, const float* __restrict__ Bm,
    const float* __restrict__ bias, float* __restrict__ out)
{
    __shared__ float As[8][GM];
    __shared__ float Bs[8][GN];
    const int bm = blockIdx.y * GM;
    const int bn = blockIdx.x * GN;
    const int tid = threadIdx.x;
    const int tx = tid & 15, ty = tid >> 4;
    const int lr = tid >> 1;          // 0..127
    const int lk = (tid & 1) * 4;     // 0 or 4

    const float* Aptr = &A [(size_t)(bm + lr) * IN_DIM + lk];
    const float* Bptr = &Bm[(size_t)(bn + lr) * IN_DIM + lk];

    float bias_r[8];
#pragma unroll
    for (int j = 0; j < 8; j++) bias_r[j] = bias[bn + tx * 8 + j];

    float tot[8][8], acc[8][8];
#pragma unroll
    for (int i = 0; i < 8; i++)
#pragma unroll
        for (int j = 0; j < 8; j++) { acc[i][j] = 0.0f; tot[i][j] = 0.0f; }
    bool first = true;

    float4 a_nx = *(const float4*)Aptr;
    float4 b_nx = *(const float4*)Bptr;

    for (int k0 = 0; k0 < IN_DIM; k0 += 8) {
        As[lk + 0][lr] = a_nx.x; As[lk + 1][lr] = a_nx.y;
        As[lk + 2][lr] = a_nx.z; As[lk + 3][lr] = a_nx.w;
        Bs[lk + 0][lr] = b_nx.x; Bs[lk + 1][lr] = b_nx.y;
        Bs[lk + 2][lr] = b_nx.z; Bs[lk + 3][lr] = b_nx.w;
        __syncthreads();
        if (k0 + 8 < IN_DIM) {
            a_nx = *(const float4*)(Aptr + k0 + 8);
            b_nx = *(const float4*)(Bptr + k0 + 8);
        }
#pragma unroll
        for (int k = 0; k < 8; k++) {
            float ar[8], br[8];
#pragma unroll
            for (int i = 0; i < 8; i++) ar[i] = As[k][ty * 8 + i];
#pragma unroll
            for (int j = 0; j < 8; j++) br[j] = Bs[k][tx * 8 + j];
#pragma unroll
            for (int i = 0; i < 8; i++)
#pragma unroll
                for (int j = 0; j < 8; j++) acc[i][j] = fmaf(ar[i], br[j], acc[i][j]);
        }
        __syncthreads();

        const int ke = k0 + 8;
        if ((ke % KC == 0) || ke == IN_DIM) {   // panel end (all boundaries %8==0)
            if (first) {
#pragma unroll
                for (int i = 0; i < 8; i++)
#pragma unroll
                    for (int j = 0; j < 8; j++) { tot[i][j] = acc[i][j]; acc[i][j] = 0.0f; }
                first = false;
            } else {
#pragma unroll
                for (int i = 0; i < 8; i++)
#pragma unroll
                    for (int j = 0; j < 8; j++) {
                        tot[i][j] = __fadd_rn(tot[i][j], acc[i][j]);
                        acc[i][j] = 0.0f;
                    }
            }
        }
    }

#pragma unroll
    for (int i = 0; i < 8; i++) {
        int row = bm + ty * 8 + i;
        float* cptr = &out[(size_t)row * N_NEUR + bn + tx * 8];
#pragma unroll
        for (int j = 0; j < 8; j++)
            cptr[j] = __fadd_rn(tot[i][j], bias_r[j]);
    }
}

// ============ 4-lane GEMM candidate: NEON-style vectorized reduction ============
// Per element: 4 lane accumulators over (absolute k) mod 4 within each kc panel,
// combined pairwise ((l0+l1)+(l2+l3)) at panel end, panels folded left-associated.
// float4-staged loads + register double buffering (values & order identical to R15).
template <int KC>
__global__ __launch_bounds__(256) void input_gemm_l4(
    const float* __restrict__ A, const float* __restrict__ Bm,
    const float* __restrict__ bias, float* __restrict__ out)
{
    __shared__ float As[8][64];
    __shared__ float Bs[8][64];
    const int bm = blockIdx.y * 64;
    const int bn = blockIdx.x * 64;
    const int tid = threadIdx.x;
    const int tx = tid & 15, ty = tid >> 4;

    // staging role: threads 0-127 stage A, 128-255 stage B (one float4 each per chunk)
    const int sr = (tid & 127) >> 1;     // row 0..63
    const int sk = (tid & 1) * 4;        // 0 or 4
    const float* Sptr = (tid < 128)
        ? &A [(size_t)(bm + sr) * IN_DIM + sk]
        : &Bm[(size_t)(bn + sr) * IN_DIM + sk];
    float (*Ss)[64] = (tid < 128) ? As : Bs;

    float tot[4][4], lac[4][4][4];
#pragma unroll
    for (int i = 0; i < 4; i++)
#pragma unroll
        for (int j = 0; j < 4; j++) {
            tot[i][j] = 0.0f;
#pragma unroll
            for (int l = 0; l < 4; l++) lac[i][j][l] = 0.0f;
        }
    bool first = true;

    float4 nx = *(const float4*)Sptr;

    for (int k0 = 0; k0 < IN_DIM; k0 += 8) {
        Ss[sk + 0][sr] = nx.x; Ss[sk + 1][sr] = nx.y;
        Ss[sk + 2][sr] = nx.z; Ss[sk + 3][sr] = nx.w;
        __syncthreads();
        if (k0 + 8 < IN_DIM) nx = *(const float4*)(Sptr + k0 + 8);
#pragma unroll
        for (int kk = 0; kk < 8; kk++) {
            const int ln = kk & 3;   // absolute k mod 4 (k0 % 8 == 0)
            float ar[4], br[4];
#pragma unroll
            for (int i = 0; i < 4; i++) ar[i] = As[kk][ty * 4 + i];
#pragma unroll
            for (int j = 0; j < 4; j++) br[j] = Bs[kk][tx * 4 + j];
#pragma unroll
            for (int i = 0; i < 4; i++)
#pragma unroll
                for (int j = 0; j < 4; j++)
                    lac[i][j][ln] = fmaf(ar[i], br[j], lac[i][j][ln]);
        }
        __syncthreads();

        const int ke = k0 + 8;
        if ((ke % KC == 0) || ke == IN_DIM) {
#pragma unroll
            for (int i = 0; i < 4; i++)
#pragma unroll
                for (int j = 0; j < 4; j++) {
                    float h = __fadd_rn(__fadd_rn(lac[i][j][0], lac[i][j][1]),
                                        __fadd_rn(lac[i][j][2], lac[i][j][3]));
                    tot[i][j] = first ? h : __fadd_rn(tot[i][j], h);
#pragma unroll
                    for (int l = 0; l < 4; l++) lac[i][j][l] = 0.0f;
                }
            first = false;
        }
    }

#pragma unroll
    for (int i = 0; i < 4; i++) {
        int row = bm + ty * 4 + i;
#pragma unroll
        for (int j = 0; j < 4; j++) {
            int col = bn + tx * 4 + j;
            out[(size_t)row * N_NEUR + col] = __fadd_rn(tot[i][j], bias[col]);
        }
    }
}

// ---------------- Wrec transpose: g_wrecT[j, n] = Wrec[n, j] ----------------
__global__ void transpose_wrec(const float* __restrict__ in) {
    __shared__ float tile[32][33];
    int x = blockIdx.x * 32 + threadIdx.x;
    int y0 = blockIdx.y * 32;
    for (int r = threadIdx.y; r < 32; r += 8)
        tile[r][threadIdx.x] = in[(size_t)(y0 + r) * N_NEUR + x];
    __syncthreads();
    int x2 = blockIdx.y * 32 + threadIdx.x;
    int y2 = blockIdx.x * 32;
    for (int r = threadIdx.y; r < 32; r += 8)
        g_wrecT[(size_t)(y2 + r) * N_NEUR + x2] = tile[threadIdx.x][r];
}

// ---------------- grid barrier (all SCAN_BLOCKS co-resident) ----------------
// The __threadfence on both leader and spinner paths emits CCTL.IVALL (gpu-scope
// fence), invalidating the SM's L1 — this is what makes the gmem list/bitmap
// exchange coherent across steps.
__device__ __forceinline__ void grid_barrier(unsigned target) {
    __syncthreads();
    if (threadIdx.x == 0) {
        __threadfence();
        unsigned v = atomicAdd(&g_bar_cnt, 1u);
        if (v == (unsigned)(SCAN_BLOCKS - 1)) {
            g_bar_cnt = 0u;
            __threadfence();
            g_bar_gen = target;
        } else {
            while (g_bar_gen < target) { }
            __threadfence();
        }
    }
    __syncthreads();
}

// per-item slow path: exact per-candidate fold semantics (identical to R15)
#define SLOW_ITEM(jj) do {                                                        \
    const float wv = colW[(size_t)(jj) * N_NEUR];                                 \
    while ((jj) >= nb1) { tot1 = __fadd_rn(tot1, acc1); acc1 = 0.0f; nb1 += 512; }\
    while ((jj) >= nb2) { tot2 = __fadd_rn(tot2, acc2); acc2 = 0.0f; nb2 += 320; }\
    while ((jj) >= nb3) { tot3 = __fadd_rn(tot3, acc3); acc3 = 0.0f; nb3 += 248; }\
    while ((jj) >= nb4) { tot4 = __fadd_rn(tot4, acc4); acc4 = 0.0f; nb4 += 200; }\
    while ((jj) >= nb6) {                                                         \
        tot6 = __fadd_rn(tot6, __fadd_rn(__fadd_rn(q40, q41), __fadd_rn(q42, q43)));\
        q40 = q41 = q42 = q43 = 0.0f; nb6 += 248; }                               \
    acc0 = __fadd_rn(acc0, wv);                                                   \
    acc1 = __fadd_rn(acc1, wv);                                                   \
    acc2 = __fadd_rn(acc2, wv);                                                   \
    acc3 = __fadd_rn(acc3, wv);                                                   \
    acc4 = __fadd_rn(acc4, wv);                                                   \
    switch ((jj) & 3) {                                                           \
      case 0: p40 = __fadd_rn(p40, wv); q40 = __fadd_rn(q40, wv); break;          \
      case 1: p41 = __fadd_rn(p41, wv); q41 = __fadd_rn(q41, wv); break;          \
      case 2: p42 = __fadd_rn(p42, wv); q42 = __fadd_rn(q42, wv); break;          \
      default: p43 = __fadd_rn(p43, wv); q43 = __fadd_rn(q43, wv); break; }       \
} while (0)

#define LANEADD(jj, wv) do {                                                      \
    switch ((jj) & 3) {                                                           \
      case 0: p40 = __fadd_rn(p40, wv); q40 = __fadd_rn(q40, wv); break;          \
      case 1: p41 = __fadd_rn(p41, wv); q41 = __fadd_rn(q41, wv); break;          \
      case 2: p42 = __fadd_rn(p42, wv); q42 = __fadd_rn(q42, wv); break;          \
      default: p43 = __fadd_rn(p43, wv); q43 = __fadd_rn(q43, wv); break; }       \
} while (0)

#define CHAIN8(a) do { a = __fadd_rn(a, w0); a = __fadd_rn(a, w1);                \
    a = __fadd_rn(a, w2); a = __fadd_rn(a, w3); a = __fadd_rn(a, w4);             \
    a = __fadd_rn(a, w5); a = __fadd_rn(a, w6); a = __fadd_rn(a, w7); } while (0)

// ---------------- persistent ensemble scan kernel ----------------
// 7 candidate orderings per cell, shared majority spike stream (>=4/7).
// Spikes exchanged as per-batch bitmaps (the warp ballot IS the bitmap word).
// Active lists built ONCE per step by blocks 0-1 (16 warps), published via gmem
// behind a grid barrier; walkers use a batched fast path (no per-item boundary
// checks unless a panel boundary falls inside the 8-item group).
__global__ __launch_bounds__(SCAN_THREADS, 1) void scan_kernel(
    const float* __restrict__ b_rec, float* __restrict__ out_spk)
{
    const int tid    = threadIdx.x;
    const int w      = tid >> 5;
    const int lane   = tid & 31;
    const int ng     = blockIdx.x >> 1;
    const int bg     = blockIdx.x & 1;
    const int n_base = ng * 32;
    const int n      = n_base + lane;
    const int b      = bg * 8 + w;
    const unsigned lmask = (1u << lane) - 1u;

    float synv[NCAND], memv[NCAND];
#pragma unroll
    for (int c = 0; c < NCAND; c++) { synv[c] = 0.0f; memv[c] = 0.0f; }
    float prev_spk = 0.0f;

    const float brec_v = b_rec[n];
    const float* __restrict__ colW = g_wrecT + n;
    const size_t cell = (size_t)b * N_NEUR + n;

    for (int t = 0; t < T_STEPS; ++t) {
        const int par = t & 1;

        // phase 1: blocks 0,1 build the 16 per-batch lists (warp w -> batch b)
        if (blockIdx.x < 2) {
            unsigned bw0 = g_bitmaps[par][b][lane];
            unsigned bw1 = g_bitmaps[par][b][32 + lane];
            int bc = 0;
#pragma unroll
            for (int r = 0; r < 64; ++r) {
                unsigned word = __shfl_sync(0xffffffffu, (r < 32) ? bw0 : bw1, r & 31);
                if ((word >> lane) & 1u)
                    g_lists[b][bc + __popc(word & lmask)] = (unsigned short)(r * 32 + lane);
                bc += __popc(word);
            }
            if (lane == 0) g_cnt[b] = bc;
            __threadfence();
        }
        grid_barrier(2u * t + 1u);

        const int cnt = g_cnt[b];
        const unsigned short* __restrict__ lst = g_lists[b];

        // ---- 7 candidate rec-sums: batched walk ----
        float acc0 = 0.0f, acc1 = 0.0f, acc2 = 0.0f, acc3 = 0.0f, acc4 = 0.0f;
        float tot1 = 0.0f, tot2 = 0.0f, tot3 = 0.0f, tot4 = 0.0f;
        float p40 = 0.0f, p41 = 0.0f, p42 = 0.0f, p43 = 0.0f;
        float q40 = 0.0f, q41 = 0.0f, q42 = 0.0f, q43 = 0.0f;
        float tot6 = 0.0f;
        int nb1 = 512, nb2 = 320, nb3 = 248, nb4 = 200, nb6 = 248;
        int nbmin = 200;

        int i = 0;
#pragma unroll 1
        while (i + 8 <= cnt) {
            const uint4 v = *(const uint4*)(lst + i);
            const int j0 = (int)(v.x & 0xFFFFu), j1 = (int)(v.x >> 16);
            const int j2 = (int)(v.y & 0xFFFFu), j3 = (int)(v.y >> 16);
            const int j4 = (int)(v.z & 0xFFFFu), j5 = (int)(v.z >> 16);
            const int j6 = (int)(v.w & 0xFFFFu), j7 = (int)(v.w >> 16);
            if (j7 < nbmin) {
                const float w0 = colW[(size_t)j0 * N_NEUR];
                const float w1 = colW[(size_t)j1 * N_NEUR];
                const float w2 = colW[(size_t)j2 * N_NEUR];
                const float w3 = colW[(size_t)j3 * N_NEUR];
                const float w4 = colW[(size_t)j4 * N_NEUR];
                const float w5 = colW[(size_t)j5 * N_NEUR];
                const float w6 = colW[(size_t)j6 * N_NEUR];
                const float w7 = colW[(size_t)j7 * N_NEUR];
                CHAIN8(acc0); CHAIN8(acc1); CHAIN8(acc2); CHAIN8(acc3); CHAIN8(acc4);
                LANEADD(j0, w0); LANEADD(j1, w1); LANEADD(j2, w2); LANEADD(j3, w3);
                LANEADD(j4, w4); LANEADD(j5, w5); LANEADD(j6, w6); LANEADD(j7, w7);
                i += 8;
            } else {
                SLOW_ITEM(j0); SLOW_ITEM(j1); SLOW_ITEM(j2); SLOW_ITEM(j3);
                SLOW_ITEM(j4); SLOW_ITEM(j5); SLOW_ITEM(j6); SLOW_ITEM(j7);
                i += 8;
                int m1 = (nb1 < nb2) ? nb1 : nb2;
                int m2 = (nb3 < nb4) ? nb3 : nb4;
                int m3 = (m1 < m2) ? m1 : m2;
                nbmin = (m3 < nb6) ? m3 : nb6;
            }
        }
#pragma unroll 1
        for (; i < cnt; ++i) {
            const int jj = lst[i];
            SLOW_ITEM(jj);
        }

        float Tv[NCAND];
        Tv[0] = acc0;                                  // tot0==0: fl(0+x)==x
        Tv[1] = __fadd_rn(tot1, acc1);
        Tv[2] = __fadd_rn(tot2, acc2);
        Tv[3] = __fadd_rn(tot3, acc3);
        Tv[4] = __fadd_rn(tot4, acc4);
        Tv[5] = __fadd_rn(__fadd_rn(p40, p41), __fadd_rn(p42, p43));
        Tv[6] = __fadd_rn(tot6, __fadd_rn(__fadd_rn(q40, q41), __fadd_rn(q42, q43)));

        // ---- state updates + majority vote (identical to R15) ----
        const float reset = prev_spk * TH_C;           // exact: 0 or 20
        const size_t toff = (size_t)t * (B_SZ * N_NEUR) + cell;
        int vcnt = 0;
#pragma unroll
        for (int c = 0; c < NCAND; c++) {
            const float cu = g_curr[c][toff];
            synv[c] = __fadd_rn(__fadd_rn(fmaf(ALPHA_C, synv[c], cu), Tv[c]), brec_v);
            memv[c] = __fsub_rn(fmaf(BETA_C, memv[c], synv[c]), reset);
            vcnt += (memv[c] > TH_C) ? 1 : 0;
        }
        const float spike = (vcnt >= 4) ? 1.0f : 0.0f;
        prev_spk = spike;
        out_spk[toff] = spike;

        // publish next-step bitmap: the warp ballot IS the bitmap word
        const unsigned bal = __ballot_sync(0xffffffffu, spike != 0.0f);
        if (lane == 0) {
            g_bitmaps[par ^ 1][b][ng] = bal;
            __threadfence();
        }
        grid_barrier(2u * t + 2u);
    }
}

// ---------------- batch-0 spike bit-vectors over time ----------------
__global__ void build_S(const float* __restrict__ spk) {
    int idx = blockIdx.x * blockDim.x + threadIdx.x;
    if (idx >= N_NEUR * 8) return;
    int n = idx >> 3, w0 = idx & 7;
    unsigned m = 0u;
#pragma unroll
    for (int k = 0; k < 32; k++) {
        int t = w0 * 32 + k;
        if (spk[(size_t)t * B_SZ * N_NEUR + n] != 0.0f) m |= (1u << k);
    }
    g_S[n][w0] = m;
}

// ---------------- STDP closed form: W = clip(W0 + delta*cnt, -1, 1) ----------------
__global__ __launch_bounds__(256) void stdp_kernel(
    const float* __restrict__ W0, float* __restrict__ Wout, float delta)
{
    const int n = blockIdx.y;
    const int j = blockIdx.x * 256 + threadIdx.x;
    __shared__ unsigned Sn[8];
    if (threadIdx.x < 8) Sn[threadIdx.x] = g_S[n][threadIdx.x];
    __syncthreads();

    unsigned Sj[8];
#pragma unroll
    for (int w = 0; w < 8; w++) Sj[w] = g_S[j][w];

    int cnt = 0;
    unsigned carry = 0u;
#pragma unroll
    for (int w = 0; w < 8; w++) {
        unsigned sh = (Sj[w] << 1) | carry;
        carry = Sj[w] >> 31;
        cnt += __popc(Sn[w] & sh);
    }

    float wv = W0[(size_t)n * N_NEUR + j];
    float r = wv + delta * (float)cnt;
    r = fmaxf(r, -1.0f);
    r = fminf(r, 1.0f);
    Wout[(size_t)n * N_NEUR + j] = r;
}

// ---------------- launch ----------------
extern "C" void kernel_launch(void* const* d_in, const int* in_sizes, int n_in,
                              void* d_out, int out_size)
{
    const float* x     = (const float*)d_in[0];
    const float* Win   = (const float*)d_in[1];
    const float* b_in  = (const float*)d_in[2];
    const float* Wrec  = (const float*)d_in[3];
    const float* b_rec = (const float*)d_in[4];
    const float* Wlsm  = (const float*)d_in[5];

    float* out_spk = (float*)d_out;
    float* out_W   = (float*)d_out + (size_t)PLANE;

    float* curr_base;
    cudaGetSymbolAddress((void**)&curr_base, g_curr);

    init_kernel<<<1, 256>>>();

    dim3 ggrid(N_NEUR / GN, (T_STEPS * B_SZ) / GM);      // (16, 32)
    input_gemm<1024><<<ggrid, 256>>>(x, Win, b_in, curr_base + 0 * (size_t)PLANE);
    input_gemm< 512><<<ggrid, 256>>>(x, Win, b_in, curr_base + 1 * (size_t)PLANE);
    input_gemm< 320><<<ggrid, 256>>>(x, Win, b_in, curr_base + 2 * (size_t)PLANE);
    input_gemm< 248><<<ggrid, 256>>>(x, Win, b_in, curr_base + 3 * (size_t)PLANE);
    input_gemm< 200><<<ggrid, 256>>>(x, Win, b_in, curr_base + 4 * (size_t)PLANE);

    dim3 lgrid(N_NEUR / 64, (T_STEPS * B_SZ) / 64);      // (32, 64)
    input_gemm_l4<1024><<<lgrid, 256>>>(x, Win, b_in, curr_base + 5 * (size_t)PLANE);
    input_gemm_l4< 248><<<lgrid, 256>>>(x, Win, b_in, curr_base + 6 * (size_t)PLANE);

    dim3 tgrid(N_NEUR / 32, N_NEUR / 32);
    transpose_wrec<<<tgrid, dim3(32, 8)>>>(Wrec);

    scan_kernel<<<SCAN_BLOCKS, SCAN_THREADS>>>(b_rec, out_spk);

    build_S<<<(N_NEUR * 8) / 256, 256>>>(out_spk);

    const float stdp_delta = (expf(-1.0f / 20.0f) - expf(1.0f / 20.0f)) * 0.001f;
    stdp_kernel<<<dim3(N_NEUR / 256, N_NEUR), 256>>>(Wlsm, out_W, stdp_delta);
}

// round 17
// speedup vs baseline: 1.8067x; 1.1602x over previous
#include <cuda_runtime.h>
#include <cstdint>

#define T_STEPS 256
#define B_SZ    16
#define IN_DIM  1024
#define N_NEUR  2048

#define ALPHA_C 0.9f
#define BETA_C  0.9f
#define TH_C    20.0f

#define NCAND 7
#define PLANE (T_STEPS * B_SZ * N_NEUR)

#define SCAN_BLOCKS  128
#define SCAN_THREADS 256

// scan shared-memory layout (dynamic): wrec stripe | lists | bitmaps | cnts
#define SM_WREC_BYTES (N_NEUR * 16 * 4)          // 131072
#define SM_LIST_OFF   SM_WREC_BYTES
#define SM_LIST_BYTES (B_SZ * N_NEUR * 2)        // 65536
#define SM_BM_OFF     (SM_LIST_OFF + SM_LIST_BYTES)   // 196608
#define SM_BM_BYTES   (B_SZ * 64 * 4)            // 4096
#define SM_CNT_OFF    (SM_BM_OFF + SM_BM_BYTES)  // 200704
#define SM_TOTAL      (SM_CNT_OFF + 64)          // 200768

// ---------------- scratch (device globals: allocation-free) ----------------
__device__ float          g_curr[NCAND][PLANE];      // 7 x 33.5 MB candidate input currents
__device__ float          g_wrecT[N_NEUR * N_NEUR];  // 16.7 MB Wrec transposed
__device__ unsigned short g_bm16[2][B_SZ][128];      // ping-pong spike bitmaps (16 neurons/ushort)
__device__ unsigned       g_S[N_NEUR][8];            // batch-0 spike bits over time
__device__ unsigned       g_bar_cnt;
__device__ volatile unsigned g_bar_gen;

// ---------------- init ----------------
__global__ void init_kernel() {
    int tid = threadIdx.x;
    for (int i = tid; i < 2 * B_SZ * 128 / 2; i += blockDim.x)   // 2048 words
        ((unsigned*)g_bm16)[i] = 0u;
    if (tid == 0) { g_bar_cnt = 0u; g_bar_gen = 0u; }
}

// ============ scalar-chain GEMM candidate: kc-panel fold via gmem staging ============
// (R15 structure, 128 regs; float4 LDS fragment reads — identical float values)
#define GM 128
#define GN 128
#define GK 8
template <int KC>
__global__ __launch_bounds__(256) void input_gemm(
    const float* __restrict__ A, const float* __restrict__ Bm,
    const float* __restrict__ bias, float* __restrict__ out)
{
    __shared__ float As[GK][GM];
    __shared__ float Bs[GK][GN];
    const int bm = blockIdx.y * GM;
    const int bn = blockIdx.x * GN;
    const int tid = threadIdx.x;
    const int tx = tid & 15, ty = tid >> 4;
    const int lr = tid >> 1;
    const int lk = (tid & 1) * 4;

    float bias_r[8];
#pragma unroll
    for (int j = 0; j < 8; j++) bias_r[j] = bias[bn + tx * 8 + j];

    int chunk_idx = 0;
    for (int p0 = 0; p0 < IN_DIM; p0 += KC, ++chunk_idx) {
        const int p_end = (p0 + KC < IN_DIM) ? (p0 + KC) : IN_DIM;

        float acc[8][8];
#pragma unroll
        for (int i = 0; i < 8; i++)
#pragma unroll
            for (int j = 0; j < 8; j++) acc[i][j] = 0.0f;

        for (int k0 = p0; k0 < p_end; k0 += GK) {
            float4 a4 = *(const float4*)&A [(size_t)(bm + lr) * IN_DIM + k0 + lk];
            float4 b4 = *(const float4*)&Bm[(size_t)(bn + lr) * IN_DIM + k0 + lk];
            As[lk + 0][lr] = a4.x; As[lk + 1][lr] = a4.y; As[lk + 2][lr] = a4.z; As[lk + 3][lr] = a4.w;
            Bs[lk + 0][lr] = b4.x; Bs[lk + 1][lr] = b4.y; Bs[lk + 2][lr] = b4.z; Bs[lk + 3][lr] = b4.w;
            __syncthreads();
#pragma unroll
            for (int k = 0; k < GK; k++) {
                float4 arl = *(const float4*)&As[k][ty * 8];
                float4 arh = *(const float4*)&As[k][ty * 8 + 4];
                float4 brl = *(const float4*)&Bs[k][tx * 8];
                float4 brh = *(const float4*)&Bs[k][tx * 8 + 4];
                float ar[8] = {arl.x, arl.y, arl.z, arl.w, arh.x, arh.y, arh.z, arh.w};
                float br[8] = {brl.x, brl.y, brl.z, brl.w, brh.x, brh.y, brh.z, brh.w};
#pragma unroll
                for (int i = 0; i < 8; i++)
#pragma unroll
                    for (int j = 0; j < 8; j++) acc[i][j] = fmaf(ar[i], br[j], acc[i][j]);
            }
            __syncthreads();
        }

        const bool first = (chunk_idx == 0);
        const bool last  = (p_end == IN_DIM);
#pragma unroll
        for (int i = 0; i < 8; i++) {
            int row = bm + ty * 8 + i;
            float* cptr = &out[(size_t)row * N_NEUR + bn + tx * 8];
#pragma unroll
            for (int j = 0; j < 8; j++) {
                float v = first ? acc[i][j] : __fadd_rn(cptr[j], acc[i][j]);
                if (last) v = __fadd_rn(v, bias_r[j]);
                cptr[j] = v;
            }
        }
    }
}

// ============ 4-lane GEMM candidate: NEON-style vectorized reduction ============
// Per element: 4 lane accumulators over (absolute k) mod 4 within each kc panel,
// pairwise combine at panel end, panels folded left-associated. float4 LDS reads.
template <int KC>
__global__ __launch_bounds__(256) void input_gemm_l4(
    const float* __restrict__ A, const float* __restrict__ Bm,
    const float* __restrict__ bias, float* __restrict__ out)
{
    __shared__ float As[8][64];
    __shared__ float Bs[8][64];
    const int bm = blockIdx.y * 64;
    const int bn = blockIdx.x * 64;
    const int tid = threadIdx.x;
    const int tx = tid & 15, ty = tid >> 4;

    const int sr = (tid & 127) >> 1;
    const int sk = (tid & 1) * 4;
    const float* Sptr = (tid < 128)
        ? &A [(size_t)(bm + sr) * IN_DIM + sk]
        : &Bm[(size_t)(bn + sr) * IN_DIM + sk];
    float (*Ss)[64] = (tid < 128) ? As : Bs;

    float tot[4][4], lac[4][4][4];
#pragma unroll
    for (int i = 0; i < 4; i++)
#pragma unroll
        for (int j = 0; j < 4; j++) {
            tot[i][j] = 0.0f;
#pragma unroll
            for (int l = 0; l < 4; l++) lac[i][j][l] = 0.0f;
        }
    bool first = true;

    float4 nx = *(const float4*)Sptr;

    for (int k0 = 0; k0 < IN_DIM; k0 += 8) {
        Ss[sk + 0][sr] = nx.x; Ss[sk + 1][sr] = nx.y;
        Ss[sk + 2][sr] = nx.z; Ss[sk + 3][sr] = nx.w;
        __syncthreads();
        if (k0 + 8 < IN_DIM) nx = *(const float4*)(Sptr + k0 + 8);
#pragma unroll
        for (int kk = 0; kk < 8; kk++) {
            const int ln = kk & 3;
            float4 a4 = *(const float4*)&As[kk][ty * 4];
            float4 b4 = *(const float4*)&Bs[kk][tx * 4];
            float ar[4] = {a4.x, a4.y, a4.z, a4.w};
            float br[4] = {b4.x, b4.y, b4.z, b4.w};
#pragma unroll
            for (int i = 0; i < 4; i++)
#pragma unroll
                for (int j = 0; j < 4; j++)
                    lac[i][j][ln] = fmaf(ar[i], br[j], lac[i][j][ln]);
        }
        __syncthreads();

        const int ke = k0 + 8;
        if ((ke % KC == 0) || ke == IN_DIM) {
#pragma unroll
            for (int i = 0; i < 4; i++)
#pragma unroll
                for (int j = 0; j < 4; j++) {
                    float h = __fadd_rn(__fadd_rn(lac[i][j][0], lac[i][j][1]),
                                        __fadd_rn(lac[i][j][2], lac[i][j][3]));
                    tot[i][j] = first ? h : __fadd_rn(tot[i][j], h);
#pragma unroll
                    for (int l = 0; l < 4; l++) lac[i][j][l] = 0.0f;
                }
            first = false;
        }
    }

#pragma unroll
    for (int i = 0; i < 4; i++) {
        int row = bm + ty * 4 + i;
#pragma unroll
        for (int j = 0; j < 4; j++) {
            int col = bn + tx * 4 + j;
            out[(size_t)row * N_NEUR + col] = __fadd_rn(tot[i][j], bias[col]);
        }
    }
}

// ---------------- Wrec transpose: g_wrecT[j, n] = Wrec[n, j] ----------------
__global__ void transpose_wrec(const float* __restrict__ in) {
    __shared__ float tile[32][33];
    int x = blockIdx.x * 32 + threadIdx.x;
    int y0 = blockIdx.y * 32;
    for (int r = threadIdx.y; r < 32; r += 8)
        tile[r][threadIdx.x] = in[(size_t)(y0 + r) * N_NEUR + x];
    __syncthreads();
    int x2 = blockIdx.y * 32 + threadIdx.x;
    int y2 = blockIdx.x * 32;
    for (int r = threadIdx.y; r < 32; r += 8)
        g_wrecT[(size_t)(y2 + r) * N_NEUR + x2] = tile[threadIdx.x][r];
}

// ---------------- grid barrier (all SCAN_BLOCKS co-resident) ----------------
// __threadfence provides release/acquire for the bitmap exchange. Its L1
// invalidation is now harmless: Wrec lives in SHARED, g_curr is streamed.
__device__ __forceinline__ void grid_barrier(unsigned target) {
    __syncthreads();
    if (threadIdx.x == 0) {
        __threadfence();
        unsigned v = atomicAdd(&g_bar_cnt, 1u);
        if (v == (unsigned)(SCAN_BLOCKS - 1)) {
            g_bar_cnt = 0u;
            __threadfence();
            g_bar_gen = target;
        } else {
            while (g_bar_gen < target) { }
            __threadfence();
        }
    }
    __syncthreads();
}

// ---------------- persistent ensemble scan kernel ----------------
// Block = 16 neurons x 16 batches (128 blocks). Thread (nl = tid&15, b = tid>>4).
// Wrec stripe (16 cols x 2048) resident in SHARED for the whole kernel.
// Per step: bitmap load (4KB) -> in-block list build -> segment-structured walk
// (7 candidate chains, exact R16 value sequences) -> vote -> bitmap publish -> 1 barrier.
__global__ __launch_bounds__(SCAN_THREADS, 1) void scan_kernel(
    const float* __restrict__ b_rec, float* __restrict__ out_spk)
{
    extern __shared__ char smem[];
    float*          s_wrec = (float*)smem;                       // [2048*16]
    unsigned short* s_list = (unsigned short*)(smem + SM_LIST_OFF); // [16][2048]
    unsigned*       s_bm   = (unsigned*)(smem + SM_BM_OFF);      // [16][64]
    int*            s_cnt  = (int*)(smem + SM_CNT_OFF);          // [16]

    const int tid    = threadIdx.x;
    const int w      = tid >> 5;
    const int lane   = tid & 31;
    const int b      = tid >> 4;          // 0..15
    const int nl     = tid & 15;          // 0..15
    const int n_base = blockIdx.x * 16;
    const int n      = n_base + nl;
    const unsigned lmask = (1u << lane) - 1u;

    // load Wrec stripe into shared (once per persistent kernel)
    for (int u = tid; u < N_NEUR * 4; u += SCAN_THREADS) {
        int j = u >> 2, c4 = (u & 3) * 4;
        float4 v = *(const float4*)&g_wrecT[(size_t)j * N_NEUR + n_base + c4];
        *(float4*)&s_wrec[j * 16 + c4] = v;
    }

    float synv[NCAND], memv[NCAND];
#pragma unroll
    for (int c = 0; c < NCAND; c++) { synv[c] = 0.0f; memv[c] = 0.0f; }
    float prev_spk = 0.0f;

    const float brec_v = b_rec[n];
    const float* __restrict__ wr = s_wrec + nl;    // item j at wr[j*16]
    const size_t cell = (size_t)b * N_NEUR + n;

    __syncthreads();

    for (int t = 0; t < T_STEPS; ++t) {
        const int par = t & 1;

        // bitmap load: 4KB = 256 uint4, one per thread
        ((uint4*)s_bm)[tid] = ((const uint4*)g_bm16[par])[tid];
        __syncthreads();

        // in-block list build: warp w builds batches 2w, 2w+1
#pragma unroll
        for (int sub = 0; sub < 2; ++sub) {
            const int bb = 2 * w + sub;
            int bc = 0;
            for (int r = 0; r < 64; ++r) {
                const unsigned word = s_bm[bb * 64 + r];
                if ((word >> lane) & 1u)
                    s_list[bb * N_NEUR + bc + __popc(word & lmask)] =
                        (unsigned short)(r * 32 + lane);
                bc += __popc(word);
            }
            if (lane == 0) s_cnt[bb] = bc;
        }
        __syncthreads();

        const int cnt = s_cnt[b];
        const unsigned short* __restrict__ lst = &s_list[b * N_NEUR];

        // ---- 7 candidate rec-sums: segment-structured walk (exact R16 values) ----
        float acc0 = 0.0f, acc1 = 0.0f, acc2 = 0.0f, acc3 = 0.0f, acc4 = 0.0f;
        float tot1 = 0.0f, tot2 = 0.0f, tot3 = 0.0f, tot4 = 0.0f, tot6 = 0.0f;
        float p40 = 0.0f, p41 = 0.0f, p42 = 0.0f, p43 = 0.0f;
        float q40 = 0.0f, q41 = 0.0f, q42 = 0.0f, q43 = 0.0f;
        int nb1 = 512, nb2 = 320, nb3 = 248, nb4 = 200;

        int i = 0;
#pragma unroll 1
        while (i < cnt) {
            const int m1 = (nb1 < nb2) ? nb1 : nb2;
            const int m2 = (nb3 < nb4) ? nb3 : nb4;
            const int B  = (m1 < m2) ? m1 : m2;
#pragma unroll 1
            while (i < cnt) {
                const int j = lst[i];
                if (j >= B) break;
                const float wv = wr[j << 4];
                acc0 = __fadd_rn(acc0, wv);
                acc1 = __fadd_rn(acc1, wv);
                acc2 = __fadd_rn(acc2, wv);
                acc3 = __fadd_rn(acc3, wv);
                acc4 = __fadd_rn(acc4, wv);
                switch (j & 3) {
                  case 0:  p40 = __fadd_rn(p40, wv); q40 = __fadd_rn(q40, wv); break;
                  case 1:  p41 = __fadd_rn(p41, wv); q41 = __fadd_rn(q41, wv); break;
                  case 2:  p42 = __fadd_rn(p42, wv); q42 = __fadd_rn(q42, wv); break;
                  default: p43 = __fadd_rn(p43, wv); q43 = __fadd_rn(q43, wv); break;
                }
                ++i;
            }
            if (i >= cnt) break;
            if (nb1 == B) { tot1 = __fadd_rn(tot1, acc1); acc1 = 0.0f; nb1 += 512; }
            if (nb2 == B) { tot2 = __fadd_rn(tot2, acc2); acc2 = 0.0f; nb2 += 320; }
            if (nb3 == B) {
                tot3 = __fadd_rn(tot3, acc3); acc3 = 0.0f;
                tot6 = __fadd_rn(tot6, __fadd_rn(__fadd_rn(q40, q41), __fadd_rn(q42, q43)));
                q40 = q41 = q42 = q43 = 0.0f;
                nb3 += 248;
            }
            if (nb4 == B) { tot4 = __fadd_rn(tot4, acc4); acc4 = 0.0f; nb4 += 200; }
        }

        float Tv[NCAND];
        Tv[0] = acc0;                                  // tot0==0: fl(0+x)==x
        Tv[1] = __fadd_rn(tot1, acc1);
        Tv[2] = __fadd_rn(tot2, acc2);
        Tv[3] = __fadd_rn(tot3, acc3);
        Tv[4] = __fadd_rn(tot4, acc4);
        Tv[5] = __fadd_rn(__fadd_rn(p40, p41), __fadd_rn(p42, p43));
        Tv[6] = __fadd_rn(tot6, __fadd_rn(__fadd_rn(q40, q41), __fadd_rn(q42, q43)));

        // ---- state updates + majority vote (identical to R15/R16) ----
        const float reset = prev_spk * TH_C;           // exact: 0 or 20
        const size_t toff = (size_t)t * (B_SZ * N_NEUR) + cell;
        int vcnt = 0;
#pragma unroll
        for (int c = 0; c < NCAND; c++) {
            const float cu = g_curr[c][toff];
            synv[c] = __fadd_rn(__fadd_rn(fmaf(ALPHA_C, synv[c], cu), Tv[c]), brec_v);
            memv[c] = __fsub_rn(fmaf(BETA_C, memv[c], synv[c]), reset);
            vcnt += (memv[c] > TH_C) ? 1 : 0;
        }
        const float spike = (vcnt >= 4) ? 1.0f : 0.0f;
        prev_spk = spike;
        out_spk[toff] = spike;

        // publish next-step bitmap: warp ballot halves = the two batches' 16-bit rows
        const unsigned bal = __ballot_sync(0xffffffffu, spike != 0.0f);
        if (lane == 0) {
            g_bm16[par ^ 1][2 * w][blockIdx.x]     = (unsigned short)(bal & 0xFFFFu);
            g_bm16[par ^ 1][2 * w + 1][blockIdx.x] = (unsigned short)(bal >> 16);
        }

        grid_barrier((unsigned)(t + 1));
    }
}

// ---------------- batch-0 spike bit-vectors over time ----------------
__global__ void build_S(const float* __restrict__ spk) {
    int idx = blockIdx.x * blockDim.x + threadIdx.x;
    if (idx >= N_NEUR * 8) return;
    int n = idx >> 3, w0 = idx & 7;
    unsigned m = 0u;
#pragma unroll
    for (int k = 0; k < 32; k++) {
        int t = w0 * 32 + k;
        if (spk[(size_t)t * B_SZ * N_NEUR + n] != 0.0f) m |= (1u << k);
    }
    g_S[n][w0] = m;
}

// ---------------- STDP closed form: W = clip(W0 + delta*cnt, -1, 1) ----------------
__global__ __launch_bounds__(256) void stdp_kernel(
    const float* __restrict__ W0, float* __restrict__ Wout, float delta)
{
    const int n = blockIdx.y;
    const int j = blockIdx.x * 256 + threadIdx.x;
    __shared__ unsigned Sn[8];
    if (threadIdx.x < 8) Sn[threadIdx.x] = g_S[n][threadIdx.x];
    __syncthreads();

    unsigned Sj[8];
#pragma unroll
    for (int w = 0; w < 8; w++) Sj[w] = g_S[j][w];

    int cnt = 0;
    unsigned carry = 0u;
#pragma unroll
    for (int w = 0; w < 8; w++) {
        unsigned sh = (Sj[w] << 1) | carry;
        carry = Sj[w] >> 31;
        cnt += __popc(Sn[w] & sh);
    }

    float wv = W0[(size_t)n * N_NEUR + j];
    float r = wv + delta * (float)cnt;
    r = fmaxf(r, -1.0f);
    r = fminf(r, 1.0f);
    Wout[(size_t)n * N_NEUR + j] = r;
}

// ---------------- launch ----------------
extern "C" void kernel_launch(void* const* d_in, const int* in_sizes, int n_in,
                              void* d_out, int out_size)
{
    const float* x     = (const float*)d_in[0];
    const float* Win   = (const float*)d_in[1];
    const float* b_in  = (const float*)d_in[2];
    const float* Wrec  = (const float*)d_in[3];
    const float* b_rec = (const float*)d_in[4];
    const float* Wlsm  = (const float*)d_in[5];

    float* out_spk = (float*)d_out;
    float* out_W   = (float*)d_out + (size_t)PLANE;

    float* curr_base;
    cudaGetSymbolAddress((void**)&curr_base, g_curr);

    static bool attr_set = false;
    if (!attr_set) {
        cudaFuncSetAttribute(scan_kernel,
                             cudaFuncAttributeMaxDynamicSharedMemorySize, SM_TOTAL);
        attr_set = true;
    }

    init_kernel<<<1, 256>>>();

    dim3 ggrid(N_NEUR / GN, (T_STEPS * B_SZ) / GM);      // (16, 32)
    input_gemm<1024><<<ggrid, 256>>>(x, Win, b_in, curr_base + 0 * (size_t)PLANE);
    input_gemm< 512><<<ggrid, 256>>>(x, Win, b_in, curr_base + 1 * (size_t)PLANE);
    input_gemm< 320><<<ggrid, 256>>>(x, Win, b_in, curr_base + 2 * (size_t)PLANE);
    input_gemm< 248><<<ggrid, 256>>>(x, Win, b_in, curr_base + 3 * (size_t)PLANE);
    input_gemm< 200><<<ggrid, 256>>>(x, Win, b_in, curr_base + 4 * (size_t)PLANE);

    dim3 lgrid(N_NEUR / 64, (T_STEPS * B_SZ) / 64);      // (32, 64)
    input_gemm_l4<1024><<<lgrid, 256>>>(x, Win, b_in, curr_base + 5 * (size_t)PLANE);
    input_gemm_l4< 248><<<lgrid, 256>>>(x, Win, b_in, curr_base + 6 * (size_t)PLANE);

    dim3 tgrid(N_NEUR / 32, N_NEUR / 32);
    transpose_wrec<<<tgrid, dim3(32, 8)>>>(Wrec);

    scan_kernel<<<SCAN_BLOCKS, SCAN_THREADS, SM_TOTAL>>>(b_rec, out_spk);

    build_S<<<(N_NEUR * 8) / 256, 256>>>(out_spk);

    const float stdp_delta = (expf(-1.0f / 20.0f) - expf(1.0f / 20.0f)) * 0.001f;
    stdp_kernel<<<dim3(N_NEUR / 256, N_NEUR), 256>>>(Wlsm, out_W, stdp_delta);
}